// round 11
// baseline (speedup 1.0000x reference)
#include <cuda_runtime.h>
#include <cstdint>
#include <cmath>

// ---------------------------------------------------------------------------
// Diffusion-LM paged attention (bidirectional) — TF32 mma.sync flash.
//   S=8 seqs, Hkv=8, GQA G=4, D=128, Q_LEN=64, ctx = 64 pages x 32 = 2048.
//   One CTA per (seq, kv-head, gqa-pair): M = 128 q-rows, 8 warps x 16 rows.
//   KV streamed in 32-token tiles, 66 tiles, online softmax.
//   R9: Q fragments register-resident for the whole kernel; ldmatrix.x4 for
//       QK-B and PV-A fragments (b16 ldmatrix distribution == tf32 fragment
//       layout for 32-bit elements). Numerics identical to R8.
// ---------------------------------------------------------------------------

#define SEQS    8
#define HKV     8
#define GQ      4
#define HDIM    128
#define QLEN    64
#define MBLK    32
#define BLKS    64
#define NTILES  66
#define SCALE_F 0.08838834764831845f

// padded smem strides (floats) — conflict-free for both ldmatrix and LDS
#define QS 132
#define KS 132
#define VS 136
#define PS 36

#define SMEM_FLOATS (128*QS + 32*KS + 32*VS + 8*16*PS)
#define SMEM_BYTES  (SMEM_FLOATS * 4)   // 120320 B

__device__ __forceinline__ float tf32f(float x) {
    uint32_t u;
    asm("cvt.rna.tf32.f32 %0, %1;" : "=r"(u) : "f"(x));
    return __uint_as_float(u);
}

__device__ __forceinline__ void mma_tf32(float* d,
                                         uint32_t a0, uint32_t a1, uint32_t a2, uint32_t a3,
                                         uint32_t b0, uint32_t b1) {
    asm volatile("mma.sync.aligned.m16n8k8.row.col.f32.tf32.tf32.f32 "
                 "{%0,%1,%2,%3}, {%4,%5,%6,%7}, {%8,%9}, {%0,%1,%2,%3};"
                 : "+f"(d[0]), "+f"(d[1]), "+f"(d[2]), "+f"(d[3])
                 : "r"(a0), "r"(a1), "r"(a2), "r"(a3), "r"(b0), "r"(b1));
}

// b16 ldmatrix x4: for 32-bit data, thread i receives float[row=i/4][col=i%4]
// of each 8x4-float matrix — exactly the tf32 m16n8k8 fragment distribution.
__device__ __forceinline__ void ldsm_x4(const float* p,
                                        uint32_t& r0, uint32_t& r1,
                                        uint32_t& r2, uint32_t& r3) {
    uint32_t a = (uint32_t)__cvta_generic_to_shared(p);
    asm volatile("ldmatrix.sync.aligned.m8n8.x4.shared.b16 {%0,%1,%2,%3}, [%4];"
                 : "=r"(r0), "=r"(r1), "=r"(r2), "=r"(r3) : "r"(a));
}

// Stage one 32-token KV tile from gmem into registers (coalesced float4).
__device__ __forceinline__ void issue_tile(int tile, int tid, int s, int h,
                                           const float* __restrict__ kc,
                                           const float* __restrict__ vc,
                                           const float* __restrict__ knew,
                                           const float* __restrict__ vnew,
                                           const int*   __restrict__ btab,
                                           float4 (&kb)[4], float4 (&vb)[4]) {
    if (tile < BLKS) {
        int bt = btab[s * BLKS + tile];
#pragma unroll
        for (int j = 0; j < 4; j++) {
            int c   = tid + 256 * j;
            int row = c >> 5;
            int d4  = (c & 31) << 2;
            int idx = ((bt * MBLK + row) * HKV + h) * HDIM + d4;
            kb[j] = *(const float4*)(kc + idx);
            vb[j] = *(const float4*)(vc + idx);
        }
    } else {
#pragma unroll
        for (int j = 0; j < 4; j++) {
            int c   = tid + 256 * j;
            int row = c >> 5;
            int d4  = (c & 31) << 2;
            int t   = (tile - BLKS) * MBLK + row;
            int idx = (s * QLEN + t) * (HKV * HDIM) + h * HDIM + d4;
            kb[j] = *(const float4*)(knew + idx);
            vb[j] = *(const float4*)(vnew + idx);
        }
    }
}

__global__ void __launch_bounds__(256, 1)
attn_tf32_kernel(const float* __restrict__ q,
                 const float* __restrict__ knew,
                 const float* __restrict__ vnew,
                 const float* __restrict__ kc,
                 const float* __restrict__ vc,
                 const int*   __restrict__ btab,
                 float*       __restrict__ out)
{
    extern __shared__ float sm[];
    float* sQ = sm;                    // [128][QS]
    float* sK = sQ + 128 * QS;         // [32][KS]
    float* sV = sK + 32 * KS;          // [32][VS]
    float* sP = sV + 32 * VS;          // [8 warps][16][PS]

    const int tid  = threadIdx.x;
    const int w    = tid >> 5;
    const int lane = tid & 31;
    const int grp  = lane >> 2;        // 0..7
    const int thr  = lane & 3;         // 0..3

    // ldmatrix lane->address mapping (matrix m = lane>>3):
    //   row  = (m&1)*8 + (lane&7),  float-col = (m>>1)*4
    const int ldrow = ((lane >> 3) & 1) * 8 + (lane & 7);
    const int ldcol = (lane >> 4) * 4;

    const int b  = blockIdx.x;
    const int s  = b >> 4;
    const int h  = (b >> 1) & 7;
    const int gp = b & 1;

    // ---- load Q into smem (scale folded in, tf32-rounded) ----
#pragma unroll
    for (int j = 0; j < 16; j++) {
        int c  = tid + 256 * j;
        int r  = c >> 5;
        int d4 = (c & 31) << 2;
        int g  = gp * 2 + (r >> 6);
        int qi = r & 63;
        float4 qv = *(const float4*)(q + (size_t)(s * QLEN + qi) * (HKV * GQ * HDIM)
                                       + (h * GQ + g) * HDIM + d4);
        *(float4*)(sQ + r * QS + d4) = make_float4(
            tf32f(qv.x * SCALE_F), tf32f(qv.y * SCALE_F),
            tf32f(qv.z * SCALE_F), tf32f(qv.w * SCALE_F));
    }
    __syncthreads();

    // ---- Q fragments -> registers, held for all 66 tiles ----
    uint32_t qf[16][4];
    {
        const float* qp = sQ + (w * 16 + ldrow) * QS + ldcol;
#pragma unroll
        for (int ks = 0; ks < 16; ks++)
            ldsm_x4(qp + 8 * ks, qf[ks][0], qf[ks][1], qf[ks][2], qf[ks][3]);
    }

    // ---- accumulators ----
    float o[16][4];
#pragma unroll
    for (int nb = 0; nb < 16; nb++) { o[nb][0] = 0.f; o[nb][1] = 0.f; o[nb][2] = 0.f; o[nb][3] = 0.f; }
    float mA = -INFINITY, mB = -INFINITY, lA = 0.f, lB = 0.f;

    float4 kb[4], vb[4];
    issue_tile(0, tid, s, h, kc, vc, knew, vnew, btab, kb, vb);

    float* sPw = sP + w * 16 * PS;
    const float* kbp = sK + ldrow * KS + ldcol;   // QK-B ldmatrix base (nb 0,1)
    const float* pap = sPw + ldrow * PS + ldcol;  // PV-A ldmatrix base
    const float* vbp = sV + thr * VS + grp;       // PV-B scalar base

    for (int t = 0; t < NTILES; t++) {
        __syncthreads();   // prior tile's sK/sV reads complete

        // staged tile -> smem, tf32-rounded
#pragma unroll
        for (int j = 0; j < 4; j++) {
            int c   = tid + 256 * j;
            int row = c >> 5;
            int d4  = (c & 31) << 2;
            *(float4*)(sK + row * KS + d4) = make_float4(
                tf32f(kb[j].x), tf32f(kb[j].y), tf32f(kb[j].z), tf32f(kb[j].w));
            *(float4*)(sV + row * VS + d4) = make_float4(
                tf32f(vb[j].x), tf32f(vb[j].y), tf32f(vb[j].z), tf32f(vb[j].w));
        }
        __syncthreads();   // tile visible

        if (t + 1 < NTILES)
            issue_tile(t + 1, tid, s, h, kc, vc, knew, vnew, btab, kb, vb);

        // ---- S = Q @ K^T  (16x32 per warp), A from registers, B via ldmatrix ----
        float sacc[4][4];
#pragma unroll
        for (int nb = 0; nb < 4; nb++) { sacc[nb][0] = 0.f; sacc[nb][1] = 0.f; sacc[nb][2] = 0.f; sacc[nb][3] = 0.f; }

#pragma unroll
        for (int ks = 0; ks < 16; ks++) {
            uint32_t b00, b01, b10, b11;   // b0(nb0), b0(nb1), b1(nb0), b1(nb1)
            uint32_t c00, c01, c10, c11;   // nb2, nb3
            ldsm_x4(kbp + 8 * ks,               b00, b01, b10, b11);
            ldsm_x4(kbp + 16 * KS + 8 * ks,     c00, c01, c10, c11);
            mma_tf32(sacc[0], qf[ks][0], qf[ks][1], qf[ks][2], qf[ks][3], b00, b10);
            mma_tf32(sacc[1], qf[ks][0], qf[ks][1], qf[ks][2], qf[ks][3], b01, b11);
            mma_tf32(sacc[2], qf[ks][0], qf[ks][1], qf[ks][2], qf[ks][3], c00, c10);
            mma_tf32(sacc[3], qf[ks][0], qf[ks][1], qf[ks][2], qf[ks][3], c01, c11);
        }

        // ---- online softmax (rows A = grp, B = grp+8 within warp tile) ----
        float rmaxA = -INFINITY, rmaxB = -INFINITY;
#pragma unroll
        for (int nb = 0; nb < 4; nb++) {
            rmaxA = fmaxf(rmaxA, fmaxf(sacc[nb][0], sacc[nb][1]));
            rmaxB = fmaxf(rmaxB, fmaxf(sacc[nb][2], sacc[nb][3]));
        }
        rmaxA = fmaxf(rmaxA, __shfl_xor_sync(0xffffffffu, rmaxA, 1));
        rmaxA = fmaxf(rmaxA, __shfl_xor_sync(0xffffffffu, rmaxA, 2));
        rmaxB = fmaxf(rmaxB, __shfl_xor_sync(0xffffffffu, rmaxB, 1));
        rmaxB = fmaxf(rmaxB, __shfl_xor_sync(0xffffffffu, rmaxB, 2));

        float mnA = fmaxf(mA, rmaxA), mnB = fmaxf(mB, rmaxB);
        float aA  = __expf(mA - mnA),  aB  = __expf(mB - mnB);
        mA = mnA; mB = mnB;

        float sumA = 0.f, sumB = 0.f;
#pragma unroll
        for (int nb = 0; nb < 4; nb++) {
            float p0 = tf32f(__expf(sacc[nb][0] - mnA));
            float p1 = tf32f(__expf(sacc[nb][1] - mnA));
            float p2 = tf32f(__expf(sacc[nb][2] - mnB));
            float p3 = tf32f(__expf(sacc[nb][3] - mnB));
            sumA += p0 + p1;  sumB += p2 + p3;
            *(float2*)(sPw + grp * PS + nb * 8 + 2 * thr)       = make_float2(p0, p1);
            *(float2*)(sPw + (grp + 8) * PS + nb * 8 + 2 * thr) = make_float2(p2, p3);
        }
        sumA += __shfl_xor_sync(0xffffffffu, sumA, 1);
        sumA += __shfl_xor_sync(0xffffffffu, sumA, 2);
        sumB += __shfl_xor_sync(0xffffffffu, sumB, 1);
        sumB += __shfl_xor_sync(0xffffffffu, sumB, 2);
        lA = lA * aA + sumA;
        lB = lB * aB + sumB;

#pragma unroll
        for (int nb = 0; nb < 16; nb++) {
            o[nb][0] *= aA; o[nb][1] *= aA;
            o[nb][2] *= aB; o[nb][3] *= aB;
        }
        __syncwarp();   // per-warp P tile written before ldmatrix reads

        // ---- O += P @ V  (16x128 per warp): A via ldmatrix, B scalar LDS ----
#pragma unroll
        for (int ks = 0; ks < 4; ks++) {
            uint32_t a0, a1, a2, a3;
            ldsm_x4(pap + 8 * ks, a0, a1, a2, a3);
            const float* vk0 = vbp + (8 * ks) * VS;
            const float* vk1 = vbp + (8 * ks + 4) * VS;
#pragma unroll
            for (int nb = 0; nb < 16; nb++) {
                uint32_t b0 = __float_as_uint(vk0[8 * nb]);
                uint32_t b1 = __float_as_uint(vk1[8 * nb]);
                mma_tf32(o[nb], a0, a1, a2, a3, b0, b1);
            }
        }
    }

    // ---- epilogue: normalize and write ----
    const float invA = 1.f / lA, invB = 1.f / lB;
    int rA = w * 16 + grp, rB = rA + 8;
    int gA = gp * 2 + (rA >> 6), gB = gp * 2 + (rB >> 6);
    size_t baseA = (size_t)(s * QLEN + (rA & 63)) * (HKV * GQ * HDIM) + (h * GQ + gA) * HDIM;
    size_t baseB = (size_t)(s * QLEN + (rB & 63)) * (HKV * GQ * HDIM) + (h * GQ + gB) * HDIM;
#pragma unroll
    for (int nb = 0; nb < 16; nb++) {
        int col = nb * 8 + 2 * thr;
        *(float2*)(out + baseA + col) = make_float2(o[nb][0] * invA, o[nb][1] * invA);
        *(float2*)(out + baseB + col) = make_float2(o[nb][2] * invB, o[nb][3] * invB);
    }
}

extern "C" void kernel_launch(void* const* d_in, const int* in_sizes, int n_in,
                              void* d_out, int out_size) {
    const float* q    = (const float*)d_in[0];
    const float* k    = (const float*)d_in[1];
    const float* v    = (const float*)d_in[2];
    const float* kc   = (const float*)d_in[3];
    const float* vc   = (const float*)d_in[4];
    const int*   btab = (const int*)d_in[5];
    float*       out  = (float*)d_out;

    cudaFuncSetAttribute(attn_tf32_kernel,
                         cudaFuncAttributeMaxDynamicSharedMemorySize, SMEM_BYTES);
    attn_tf32_kernel<<<SEQS * HKV * (GQ / 2), 256, SMEM_BYTES>>>(
        q, k, v, kc, vc, btab, out);
}

// round 12
// speedup vs baseline: 1.0004x; 1.0004x over previous
#include <cuda_runtime.h>
#include <cstdint>
#include <cmath>

// ---------------------------------------------------------------------------
// Diffusion-LM paged attention (bidirectional) — TF32 mma.sync flash.
//   S=8 seqs, Hkv=8, GQA G=4, D=128, Q_LEN=64, ctx = 64 pages x 32 = 2048.
//   One CTA per (seq, kv-head, gqa-pair): M = 128 q-rows, 8 warps x 16 rows.
//   KV streamed in 32-token tiles, 66 tiles, online softmax.
//   R9: Q fragments register-resident for the whole kernel; ldmatrix.x4 for
//       QK-B and PV-A fragments (b16 ldmatrix distribution == tf32 fragment
//       layout for 32-bit elements). Numerics identical to R8.
// ---------------------------------------------------------------------------

#define SEQS    8
#define HKV     8
#define GQ      4
#define HDIM    128
#define QLEN    64
#define MBLK    32
#define BLKS    64
#define NTILES  66
#define SCALE_F 0.08838834764831845f

// padded smem strides (floats) — conflict-free for both ldmatrix and LDS
#define QS 132
#define KS 132
#define VS 136
#define PS 36

#define SMEM_FLOATS (128*QS + 32*KS + 32*VS + 8*16*PS)
#define SMEM_BYTES  (SMEM_FLOATS * 4)   // 120320 B

__device__ __forceinline__ float tf32f(float x) {
    uint32_t u;
    asm("cvt.rna.tf32.f32 %0, %1;" : "=r"(u) : "f"(x));
    return __uint_as_float(u);
}

__device__ __forceinline__ void mma_tf32(float* d,
                                         uint32_t a0, uint32_t a1, uint32_t a2, uint32_t a3,
                                         uint32_t b0, uint32_t b1) {
    asm volatile("mma.sync.aligned.m16n8k8.row.col.f32.tf32.tf32.f32 "
                 "{%0,%1,%2,%3}, {%4,%5,%6,%7}, {%8,%9}, {%0,%1,%2,%3};"
                 : "+f"(d[0]), "+f"(d[1]), "+f"(d[2]), "+f"(d[3])
                 : "r"(a0), "r"(a1), "r"(a2), "r"(a3), "r"(b0), "r"(b1));
}

// b16 ldmatrix x4: for 32-bit data, thread i receives float[row=i/4][col=i%4]
// of each 8x4-float matrix — exactly the tf32 m16n8k8 fragment distribution.
__device__ __forceinline__ void ldsm_x4(const float* p,
                                        uint32_t& r0, uint32_t& r1,
                                        uint32_t& r2, uint32_t& r3) {
    uint32_t a = (uint32_t)__cvta_generic_to_shared(p);
    asm volatile("ldmatrix.sync.aligned.m8n8.x4.shared.b16 {%0,%1,%2,%3}, [%4];"
                 : "=r"(r0), "=r"(r1), "=r"(r2), "=r"(r3) : "r"(a));
}

// Stage one 32-token KV tile from gmem into registers (coalesced float4).
__device__ __forceinline__ void issue_tile(int tile, int tid, int s, int h,
                                           const float* __restrict__ kc,
                                           const float* __restrict__ vc,
                                           const float* __restrict__ knew,
                                           const float* __restrict__ vnew,
                                           const int*   __restrict__ btab,
                                           float4 (&kb)[4], float4 (&vb)[4]) {
    if (tile < BLKS) {
        int bt = btab[s * BLKS + tile];
#pragma unroll
        for (int j = 0; j < 4; j++) {
            int c   = tid + 256 * j;
            int row = c >> 5;
            int d4  = (c & 31) << 2;
            int idx = ((bt * MBLK + row) * HKV + h) * HDIM + d4;
            kb[j] = *(const float4*)(kc + idx);
            vb[j] = *(const float4*)(vc + idx);
        }
    } else {
#pragma unroll
        for (int j = 0; j < 4; j++) {
            int c   = tid + 256 * j;
            int row = c >> 5;
            int d4  = (c & 31) << 2;
            int t   = (tile - BLKS) * MBLK + row;
            int idx = (s * QLEN + t) * (HKV * HDIM) + h * HDIM + d4;
            kb[j] = *(const float4*)(knew + idx);
            vb[j] = *(const float4*)(vnew + idx);
        }
    }
}

__global__ void __launch_bounds__(256, 1)
attn_tf32_kernel(const float* __restrict__ q,
                 const float* __restrict__ knew,
                 const float* __restrict__ vnew,
                 const float* __restrict__ kc,
                 const float* __restrict__ vc,
                 const int*   __restrict__ btab,
                 float*       __restrict__ out)
{
    extern __shared__ float sm[];
    float* sQ = sm;                    // [128][QS]
    float* sK = sQ + 128 * QS;         // [32][KS]
    float* sV = sK + 32 * KS;          // [32][VS]
    float* sP = sV + 32 * VS;          // [8 warps][16][PS]

    const int tid  = threadIdx.x;
    const int w    = tid >> 5;
    const int lane = tid & 31;
    const int grp  = lane >> 2;        // 0..7
    const int thr  = lane & 3;         // 0..3

    // ldmatrix lane->address mapping (matrix m = lane>>3):
    //   row  = (m&1)*8 + (lane&7),  float-col = (m>>1)*4
    const int ldrow = ((lane >> 3) & 1) * 8 + (lane & 7);
    const int ldcol = (lane >> 4) * 4;

    const int b  = blockIdx.x;
    const int s  = b >> 4;
    const int h  = (b >> 1) & 7;
    const int gp = b & 1;

    // ---- load Q into smem (scale folded in, tf32-rounded) ----
#pragma unroll
    for (int j = 0; j < 16; j++) {
        int c  = tid + 256 * j;
        int r  = c >> 5;
        int d4 = (c & 31) << 2;
        int g  = gp * 2 + (r >> 6);
        int qi = r & 63;
        float4 qv = *(const float4*)(q + (size_t)(s * QLEN + qi) * (HKV * GQ * HDIM)
                                       + (h * GQ + g) * HDIM + d4);
        *(float4*)(sQ + r * QS + d4) = make_float4(
            tf32f(qv.x * SCALE_F), tf32f(qv.y * SCALE_F),
            tf32f(qv.z * SCALE_F), tf32f(qv.w * SCALE_F));
    }
    __syncthreads();

    // ---- Q fragments -> registers, held for all 66 tiles ----
    uint32_t qf[16][4];
    {
        const float* qp = sQ + (w * 16 + ldrow) * QS + ldcol;
#pragma unroll
        for (int ks = 0; ks < 16; ks++)
            ldsm_x4(qp + 8 * ks, qf[ks][0], qf[ks][1], qf[ks][2], qf[ks][3]);
    }

    // ---- accumulators ----
    float o[16][4];
#pragma unroll
    for (int nb = 0; nb < 16; nb++) { o[nb][0] = 0.f; o[nb][1] = 0.f; o[nb][2] = 0.f; o[nb][3] = 0.f; }
    float mA = -INFINITY, mB = -INFINITY, lA = 0.f, lB = 0.f;

    float4 kb[4], vb[4];
    issue_tile(0, tid, s, h, kc, vc, knew, vnew, btab, kb, vb);

    float* sPw = sP + w * 16 * PS;
    const float* kbp = sK + ldrow * KS + ldcol;   // QK-B ldmatrix base (nb 0,1)
    const float* pap = sPw + ldrow * PS + ldcol;  // PV-A ldmatrix base
    const float* vbp = sV + thr * VS + grp;       // PV-B scalar base

    for (int t = 0; t < NTILES; t++) {
        __syncthreads();   // prior tile's sK/sV reads complete

        // staged tile -> smem, tf32-rounded
#pragma unroll
        for (int j = 0; j < 4; j++) {
            int c   = tid + 256 * j;
            int row = c >> 5;
            int d4  = (c & 31) << 2;
            *(float4*)(sK + row * KS + d4) = make_float4(
                tf32f(kb[j].x), tf32f(kb[j].y), tf32f(kb[j].z), tf32f(kb[j].w));
            *(float4*)(sV + row * VS + d4) = make_float4(
                tf32f(vb[j].x), tf32f(vb[j].y), tf32f(vb[j].z), tf32f(vb[j].w));
        }
        __syncthreads();   // tile visible

        if (t + 1 < NTILES)
            issue_tile(t + 1, tid, s, h, kc, vc, knew, vnew, btab, kb, vb);

        // ---- S = Q @ K^T  (16x32 per warp), A from registers, B via ldmatrix ----
        float sacc[4][4];
#pragma unroll
        for (int nb = 0; nb < 4; nb++) { sacc[nb][0] = 0.f; sacc[nb][1] = 0.f; sacc[nb][2] = 0.f; sacc[nb][3] = 0.f; }

#pragma unroll
        for (int ks = 0; ks < 16; ks++) {
            uint32_t b00, b01, b10, b11;   // b0(nb0), b0(nb1), b1(nb0), b1(nb1)
            uint32_t c00, c01, c10, c11;   // nb2, nb3
            ldsm_x4(kbp + 8 * ks,               b00, b01, b10, b11);
            ldsm_x4(kbp + 16 * KS + 8 * ks,     c00, c01, c10, c11);
            mma_tf32(sacc[0], qf[ks][0], qf[ks][1], qf[ks][2], qf[ks][3], b00, b10);
            mma_tf32(sacc[1], qf[ks][0], qf[ks][1], qf[ks][2], qf[ks][3], b01, b11);
            mma_tf32(sacc[2], qf[ks][0], qf[ks][1], qf[ks][2], qf[ks][3], c00, c10);
            mma_tf32(sacc[3], qf[ks][0], qf[ks][1], qf[ks][2], qf[ks][3], c01, c11);
        }

        // ---- online softmax (rows A = grp, B = grp+8 within warp tile) ----
        float rmaxA = -INFINITY, rmaxB = -INFINITY;
#pragma unroll
        for (int nb = 0; nb < 4; nb++) {
            rmaxA = fmaxf(rmaxA, fmaxf(sacc[nb][0], sacc[nb][1]));
            rmaxB = fmaxf(rmaxB, fmaxf(sacc[nb][2], sacc[nb][3]));
        }
        rmaxA = fmaxf(rmaxA, __shfl_xor_sync(0xffffffffu, rmaxA, 1));
        rmaxA = fmaxf(rmaxA, __shfl_xor_sync(0xffffffffu, rmaxA, 2));
        rmaxB = fmaxf(rmaxB, __shfl_xor_sync(0xffffffffu, rmaxB, 1));
        rmaxB = fmaxf(rmaxB, __shfl_xor_sync(0xffffffffu, rmaxB, 2));

        float mnA = fmaxf(mA, rmaxA), mnB = fmaxf(mB, rmaxB);
        float aA  = __expf(mA - mnA),  aB  = __expf(mB - mnB);
        mA = mnA; mB = mnB;

        float sumA = 0.f, sumB = 0.f;
#pragma unroll
        for (int nb = 0; nb < 4; nb++) {
            float p0 = tf32f(__expf(sacc[nb][0] - mnA));
            float p1 = tf32f(__expf(sacc[nb][1] - mnA));
            float p2 = tf32f(__expf(sacc[nb][2] - mnB));
            float p3 = tf32f(__expf(sacc[nb][3] - mnB));
            sumA += p0 + p1;  sumB += p2 + p3;
            *(float2*)(sPw + grp * PS + nb * 8 + 2 * thr)       = make_float2(p0, p1);
            *(float2*)(sPw + (grp + 8) * PS + nb * 8 + 2 * thr) = make_float2(p2, p3);
        }
        sumA += __shfl_xor_sync(0xffffffffu, sumA, 1);
        sumA += __shfl_xor_sync(0xffffffffu, sumA, 2);
        sumB += __shfl_xor_sync(0xffffffffu, sumB, 1);
        sumB += __shfl_xor_sync(0xffffffffu, sumB, 2);
        lA = lA * aA + sumA;
        lB = lB * aB + sumB;

#pragma unroll
        for (int nb = 0; nb < 16; nb++) {
            o[nb][0] *= aA; o[nb][1] *= aA;
            o[nb][2] *= aB; o[nb][3] *= aB;
        }
        __syncwarp();   // per-warp P tile written before ldmatrix reads

        // ---- O += P @ V  (16x128 per warp): A via ldmatrix, B scalar LDS ----
#pragma unroll
        for (int ks = 0; ks < 4; ks++) {
            uint32_t a0, a1, a2, a3;
            ldsm_x4(pap + 8 * ks, a0, a1, a2, a3);
            const float* vk0 = vbp + (8 * ks) * VS;
            const float* vk1 = vbp + (8 * ks + 4) * VS;
#pragma unroll
            for (int nb = 0; nb < 16; nb++) {
                uint32_t b0 = __float_as_uint(vk0[8 * nb]);
                uint32_t b1 = __float_as_uint(vk1[8 * nb]);
                mma_tf32(o[nb], a0, a1, a2, a3, b0, b1);
            }
        }
    }

    // ---- epilogue: normalize and write ----
    const float invA = 1.f / lA, invB = 1.f / lB;
    int rA = w * 16 + grp, rB = rA + 8;
    int gA = gp * 2 + (rA >> 6), gB = gp * 2 + (rB >> 6);
    size_t baseA = (size_t)(s * QLEN + (rA & 63)) * (HKV * GQ * HDIM) + (h * GQ + gA) * HDIM;
    size_t baseB = (size_t)(s * QLEN + (rB & 63)) * (HKV * GQ * HDIM) + (h * GQ + gB) * HDIM;
#pragma unroll
    for (int nb = 0; nb < 16; nb++) {
        int col = nb * 8 + 2 * thr;
        *(float2*)(out + baseA + col) = make_float2(o[nb][0] * invA, o[nb][1] * invA);
        *(float2*)(out + baseB + col) = make_float2(o[nb][2] * invB, o[nb][3] * invB);
    }
}

extern "C" void kernel_launch(void* const* d_in, const int* in_sizes, int n_in,
                              void* d_out, int out_size) {
    const float* q    = (const float*)d_in[0];
    const float* k    = (const float*)d_in[1];
    const float* v    = (const float*)d_in[2];
    const float* kc   = (const float*)d_in[3];
    const float* vc   = (const float*)d_in[4];
    const int*   btab = (const int*)d_in[5];
    float*       out  = (float*)d_out;

    cudaFuncSetAttribute(attn_tf32_kernel,
                         cudaFuncAttributeMaxDynamicSharedMemorySize, SMEM_BYTES);
    attn_tf32_kernel<<<SEQS * HKV * (GQ / 2), 256, SMEM_BYTES>>>(
        q, k, v, kc, vc, btab, out);
}

// round 13
// speedup vs baseline: 1.0557x; 1.0553x over previous
#include <cuda_runtime.h>
#include <cstdint>
#include <cmath>

// ---------------------------------------------------------------------------
// Diffusion-LM paged attention (bidirectional) — TF32 mma.sync flash.
//   S=8 seqs, Hkv=8, GQA G=4, D=128, Q_LEN=64, ctx = 64 pages x 32 = 2048.
//   One CTA per (seq, kv-head, gqa-pair): M = 128 q-rows, 8 warps x 16 rows.
//   KV streamed in 32-token tiles, 66 tiles, online softmax.
//   R12: cp.async double-buffered K/V tiles (no staging regs, no K/V cvt —
//        MMA's native tf32 truncation used for K/V; Q and P stay RNA-rounded).
//        Q fragments register-resident; ldmatrix.x4 for QK-B and PV-A.
// ---------------------------------------------------------------------------

#define SEQS    8
#define HKV     8
#define GQ      4
#define HDIM    128
#define QLEN    64
#define MBLK    32
#define BLKS    64
#define NTILES  66
#define SCALE_F 0.08838834764831845f

// padded smem strides (floats) — conflict-free for ldmatrix and scalar LDS
#define QS 132
#define KS 132
#define VS 136
#define PS 36

// sQ + double-buffered (sK,sV) + per-warp P
#define SMEM_FLOATS (128*QS + 2*(32*KS + 32*VS) + 8*16*PS)
#define SMEM_BYTES  (SMEM_FLOATS * 4)   // 154624 B

__device__ __forceinline__ float tf32f(float x) {
    uint32_t u;
    asm("cvt.rna.tf32.f32 %0, %1;" : "=r"(u) : "f"(x));
    return __uint_as_float(u);
}

__device__ __forceinline__ void mma_tf32(float* d,
                                         uint32_t a0, uint32_t a1, uint32_t a2, uint32_t a3,
                                         uint32_t b0, uint32_t b1) {
    asm volatile("mma.sync.aligned.m16n8k8.row.col.f32.tf32.tf32.f32 "
                 "{%0,%1,%2,%3}, {%4,%5,%6,%7}, {%8,%9}, {%0,%1,%2,%3};"
                 : "+f"(d[0]), "+f"(d[1]), "+f"(d[2]), "+f"(d[3])
                 : "r"(a0), "r"(a1), "r"(a2), "r"(a3), "r"(b0), "r"(b1));
}

// b16 ldmatrix x4: for 32-bit data, thread i receives float[row=i/4][col=i%4]
// of each 8x4-float matrix — exactly the tf32 m16n8k8 fragment distribution.
__device__ __forceinline__ void ldsm_x4(const float* p,
                                        uint32_t& r0, uint32_t& r1,
                                        uint32_t& r2, uint32_t& r3) {
    uint32_t a = (uint32_t)__cvta_generic_to_shared(p);
    asm volatile("ldmatrix.sync.aligned.m8n8.x4.shared.b16 {%0,%1,%2,%3}, [%4];"
                 : "=r"(r0), "=r"(r1), "=r"(r2), "=r"(r3) : "r"(a));
}

__device__ __forceinline__ void cp16(float* dst, const float* src) {
    uint32_t d = (uint32_t)__cvta_generic_to_shared(dst);
    asm volatile("cp.async.cg.shared.global [%0], [%1], 16;" :: "r"(d), "l"(src));
}

// Async-copy one 32-token KV tile (gmem -> smem buffer), then commit group.
__device__ __forceinline__ void cp_tile(int tile, int tid, int s, int h,
                                        const float* __restrict__ kc,
                                        const float* __restrict__ vc,
                                        const float* __restrict__ knew,
                                        const float* __restrict__ vnew,
                                        const int*   __restrict__ btab,
                                        float* dK, float* dV) {
    if (tile < BLKS) {
        int bt = __ldg(btab + s * BLKS + tile);
#pragma unroll
        for (int j = 0; j < 4; j++) {
            int c   = tid + 256 * j;
            int row = c >> 5;
            int d4  = (c & 31) << 2;
            int idx = ((bt * MBLK + row) * HKV + h) * HDIM + d4;
            cp16(dK + row * KS + d4, kc + idx);
            cp16(dV + row * VS + d4, vc + idx);
        }
    } else {
#pragma unroll
        for (int j = 0; j < 4; j++) {
            int c   = tid + 256 * j;
            int row = c >> 5;
            int d4  = (c & 31) << 2;
            int t2  = (tile - BLKS) * MBLK + row;
            int idx = (s * QLEN + t2) * (HKV * HDIM) + h * HDIM + d4;
            cp16(dK + row * KS + d4, knew + idx);
            cp16(dV + row * VS + d4, vnew + idx);
        }
    }
    asm volatile("cp.async.commit_group;");
}

__global__ void __launch_bounds__(256, 1)
attn_tf32_kernel(const float* __restrict__ q,
                 const float* __restrict__ knew,
                 const float* __restrict__ vnew,
                 const float* __restrict__ kc,
                 const float* __restrict__ vc,
                 const int*   __restrict__ btab,
                 float*       __restrict__ out)
{
    extern __shared__ float sm[];
    float* sQ  = sm;                     // [128][QS]
    float* sK0 = sQ  + 128 * QS;         // [32][KS] buffer 0
    float* sV0 = sK0 + 32 * KS;          // [32][VS]
    float* sK1 = sV0 + 32 * VS;          // [32][KS] buffer 1
    float* sV1 = sK1 + 32 * KS;          // [32][VS]
    float* sP  = sV1 + 32 * VS;          // [8 warps][16][PS]

    const int tid  = threadIdx.x;
    const int w    = tid >> 5;
    const int lane = tid & 31;
    const int grp  = lane >> 2;          // 0..7
    const int thr  = lane & 3;           // 0..3

    // ldmatrix lane->address mapping (matrix m = lane>>3):
    //   row = (m&1)*8 + (lane&7),  float-col = (m>>1)*4
    const int ldrow = ((lane >> 3) & 1) * 8 + (lane & 7);
    const int ldcol = (lane >> 4) * 4;

    const int b  = blockIdx.x;
    const int s  = b >> 4;
    const int h  = (b >> 1) & 7;
    const int gp = b & 1;

    // ---- prefetch tiles 0 and 1 ----
    cp_tile(0, tid, s, h, kc, vc, knew, vnew, btab, sK0, sV0);
    cp_tile(1, tid, s, h, kc, vc, knew, vnew, btab, sK1, sV1);

    // ---- load Q into smem (scale folded in, tf32 RNA-rounded) ----
#pragma unroll
    for (int j = 0; j < 16; j++) {
        int c  = tid + 256 * j;
        int r  = c >> 5;
        int d4 = (c & 31) << 2;
        int g  = gp * 2 + (r >> 6);
        int qi = r & 63;
        float4 qv = *(const float4*)(q + (size_t)(s * QLEN + qi) * (HKV * GQ * HDIM)
                                       + (h * GQ + g) * HDIM + d4);
        *(float4*)(sQ + r * QS + d4) = make_float4(
            tf32f(qv.x * SCALE_F), tf32f(qv.y * SCALE_F),
            tf32f(qv.z * SCALE_F), tf32f(qv.w * SCALE_F));
    }
    __syncthreads();

    // ---- Q fragments -> registers, held for all 66 tiles ----
    uint32_t qf[16][4];
    {
        const float* qp = sQ + (w * 16 + ldrow) * QS + ldcol;
#pragma unroll
        for (int ks = 0; ks < 16; ks++)
            ldsm_x4(qp + 8 * ks, qf[ks][0], qf[ks][1], qf[ks][2], qf[ks][3]);
    }

    // ---- accumulators ----
    float o[16][4];
#pragma unroll
    for (int nb = 0; nb < 16; nb++) { o[nb][0] = 0.f; o[nb][1] = 0.f; o[nb][2] = 0.f; o[nb][3] = 0.f; }
    float mA = -INFINITY, mB = -INFINITY, lA = 0.f, lB = 0.f;

    float* sPw = sP + w * 16 * PS;
    const float* pap = sPw + ldrow * PS + ldcol;   // PV-A ldmatrix base

    for (int t = 0; t < NTILES; t++) {
        // wait for tile t's cp.async group (keep t+1 in flight)
        if (t == NTILES - 1) asm volatile("cp.async.wait_all;" ::: "memory");
        else                 asm volatile("cp.async.wait_group 1;" ::: "memory");
        __syncthreads();     // visibility of tile t to all warps

        const float* sKt = (t & 1) ? sK1 : sK0;
        const float* sVt = (t & 1) ? sV1 : sV0;
        const float* kbp = sKt + ldrow * KS + ldcol;
        const float* vbp = sVt + thr * VS + grp;

        // ---- S = Q @ K^T  (16x32 per warp): A regs, B via ldmatrix ----
        float sacc[4][4];
#pragma unroll
        for (int nb = 0; nb < 4; nb++) { sacc[nb][0] = 0.f; sacc[nb][1] = 0.f; sacc[nb][2] = 0.f; sacc[nb][3] = 0.f; }

#pragma unroll
        for (int ks = 0; ks < 16; ks++) {
            uint32_t b00, b01, b10, b11;   // nb0/nb1
            uint32_t c00, c01, c10, c11;   // nb2/nb3
            ldsm_x4(kbp + 8 * ks,           b00, b01, b10, b11);
            ldsm_x4(kbp + 16 * KS + 8 * ks, c00, c01, c10, c11);
            mma_tf32(sacc[0], qf[ks][0], qf[ks][1], qf[ks][2], qf[ks][3], b00, b10);
            mma_tf32(sacc[1], qf[ks][0], qf[ks][1], qf[ks][2], qf[ks][3], b01, b11);
            mma_tf32(sacc[2], qf[ks][0], qf[ks][1], qf[ks][2], qf[ks][3], c00, c10);
            mma_tf32(sacc[3], qf[ks][0], qf[ks][1], qf[ks][2], qf[ks][3], c01, c11);
        }

        // ---- online softmax (rows A = grp, B = grp+8) ----
        float rmaxA = -INFINITY, rmaxB = -INFINITY;
#pragma unroll
        for (int nb = 0; nb < 4; nb++) {
            rmaxA = fmaxf(rmaxA, fmaxf(sacc[nb][0], sacc[nb][1]));
            rmaxB = fmaxf(rmaxB, fmaxf(sacc[nb][2], sacc[nb][3]));
        }
        rmaxA = fmaxf(rmaxA, __shfl_xor_sync(0xffffffffu, rmaxA, 1));
        rmaxA = fmaxf(rmaxA, __shfl_xor_sync(0xffffffffu, rmaxA, 2));
        rmaxB = fmaxf(rmaxB, __shfl_xor_sync(0xffffffffu, rmaxB, 1));
        rmaxB = fmaxf(rmaxB, __shfl_xor_sync(0xffffffffu, rmaxB, 2));

        float mnA = fmaxf(mA, rmaxA), mnB = fmaxf(mB, rmaxB);
        float aA  = __expf(mA - mnA),  aB  = __expf(mB - mnB);
        mA = mnA; mB = mnB;

        float sumA = 0.f, sumB = 0.f;
#pragma unroll
        for (int nb = 0; nb < 4; nb++) {
            float p0 = tf32f(__expf(sacc[nb][0] - mnA));
            float p1 = tf32f(__expf(sacc[nb][1] - mnA));
            float p2 = tf32f(__expf(sacc[nb][2] - mnB));
            float p3 = tf32f(__expf(sacc[nb][3] - mnB));
            sumA += p0 + p1;  sumB += p2 + p3;
            *(float2*)(sPw + grp * PS + nb * 8 + 2 * thr)       = make_float2(p0, p1);
            *(float2*)(sPw + (grp + 8) * PS + nb * 8 + 2 * thr) = make_float2(p2, p3);
        }
        sumA += __shfl_xor_sync(0xffffffffu, sumA, 1);
        sumA += __shfl_xor_sync(0xffffffffu, sumA, 2);
        sumB += __shfl_xor_sync(0xffffffffu, sumB, 1);
        sumB += __shfl_xor_sync(0xffffffffu, sumB, 2);
        lA = lA * aA + sumA;
        lB = lB * aB + sumB;

#pragma unroll
        for (int nb = 0; nb < 16; nb++) {
            o[nb][0] *= aA; o[nb][1] *= aA;
            o[nb][2] *= aB; o[nb][3] *= aB;
        }
        __syncwarp();   // per-warp P tile written before ldmatrix reads

        // ---- O += P @ V  (16x128 per warp): A via ldmatrix, B scalar LDS ----
#pragma unroll
        for (int ks = 0; ks < 4; ks++) {
            uint32_t a0, a1, a2, a3;
            ldsm_x4(pap + 8 * ks, a0, a1, a2, a3);
            const float* vk0 = vbp + (8 * ks) * VS;
            const float* vk1 = vbp + (8 * ks + 4) * VS;
#pragma unroll
            for (int nb = 0; nb < 16; nb++) {
                uint32_t b0 = __float_as_uint(vk0[8 * nb]);
                uint32_t b1 = __float_as_uint(vk1[8 * nb]);
                mma_tf32(o[nb], a0, a1, a2, a3, b0, b1);
            }
        }

        __syncthreads();   // all warps done reading buffer (t&1) before refill
        if (t + 2 < NTILES)
            cp_tile(t + 2, tid, s, h, kc, vc, knew, vnew, btab,
                    (t & 1) ? sK1 : sK0, (t & 1) ? sV1 : sV0);
    }

    // ---- epilogue: normalize and write ----
    const float invA = 1.f / lA, invB = 1.f / lB;
    int rA = w * 16 + grp, rB = rA + 8;
    int gA = gp * 2 + (rA >> 6), gB = gp * 2 + (rB >> 6);
    size_t baseA = (size_t)(s * QLEN + (rA & 63)) * (HKV * GQ * HDIM) + (h * GQ + gA) * HDIM;
    size_t baseB = (size_t)(s * QLEN + (rB & 63)) * (HKV * GQ * HDIM) + (h * GQ + gB) * HDIM;
#pragma unroll
    for (int nb = 0; nb < 16; nb++) {
        int col = nb * 8 + 2 * thr;
        *(float2*)(out + baseA + col) = make_float2(o[nb][0] * invA, o[nb][1] * invA);
        *(float2*)(out + baseB + col) = make_float2(o[nb][2] * invB, o[nb][3] * invB);
    }
}

extern "C" void kernel_launch(void* const* d_in, const int* in_sizes, int n_in,
                              void* d_out, int out_size) {
    const float* q    = (const float*)d_in[0];
    const float* k    = (const float*)d_in[1];
    const float* v    = (const float*)d_in[2];
    const float* kc   = (const float*)d_in[3];
    const float* vc   = (const float*)d_in[4];
    const int*   btab = (const int*)d_in[5];
    float*       out  = (float*)d_out;

    cudaFuncSetAttribute(attn_tf32_kernel,
                         cudaFuncAttributeMaxDynamicSharedMemorySize, SMEM_BYTES);
    attn_tf32_kernel<<<SEQS * HKV * (GQ / 2), 256, SMEM_BYTES>>>(
        q, k, v, kc, vc, btab, out);
}